// round 11
// baseline (speedup 1.0000x reference)
#include <cuda_runtime.h>
#include <cuda_fp16.h>
#include <math.h>

#define Nn  100000
#define Ee  1600000
#define Bb  4096
#define FIN 25
#define Hh  128
#define EPSf 1e-5f

// ---------------- scratch (static __device__ — allocation-free) ----------------
__device__ __align__(16) float  g_h [Nn * Hh];   // pre-BN hidden (h1, then h2)
__device__ __align__(16) __half g_xwh[Nn * Hh];  // GEMM2 output fp16 (pre-agg)
__device__ __align__(16) __half g_W2h[Hh * Hh];  // W2 transposed fp16: [n][k]
__device__ __align__(16) float  g_ax[Nn * 32];   // aggregated 25-dim input (padded)
__device__ int    g_deg[Nn];
__device__ int    g_cursor[Nn];
__device__ float  g_dinv[Nn];
__device__ int    g_rowstart[Nn + 1];
__device__ __align__(8) int2 g_csr[Ee];          // {src, coef as float bits}
__device__ float  g_bnsum[Hh];
__device__ float  g_bnsq [Hh];
__device__ float  g_bnA[Hh];
__device__ float  g_bnB[Hh];
__device__ int    g_bsum[64];
__device__ int    g_bcnt[Bb];
__device__ int    g_boff[Bb];

// runtime-resolved input handles
__device__ int    g_ei64;
__device__ int    g_batch64;
__device__ const float* gp_b[2];
__device__ const float* gp_g[2];
__device__ const float* gp_be[2];

__device__ __forceinline__ int ld_idx(const void* p, long long i, int is64) {
    return is64 ? (int)((const long long*)p)[i] : ((const int*)p)[i];
}

// ---------------- setup: zero scratch + convert W2 to fp16^T ----------------
__global__ void k_setup(const float* __restrict__ W2) {
    int i = blockIdx.x * blockDim.x + threadIdx.x;
    if (i < Nn) { g_deg[i] = 0; g_cursor[i] = 0; }
    if (i < Bb) g_bcnt[i] = 0;
    if (i < Hh) { g_bnsum[i] = 0.f; g_bnsq[i] = 0.f; }
    if (i < Hh * Hh) {              // i = k*128 + n
        int k = i >> 7, n = i & 127;
        g_W2h[n * Hh + k] = __float2half(W2[i]);
    }
}

// ---------------- detect index width + classify 128-vectors ----------------
__global__ void k_classify(const void* ei, const void* batch,
                           const float* c0, const float* c1, const float* c2,
                           const float* c3, const float* c4, const float* c5) {
    int t = threadIdx.x, lane = t & 31, w = t >> 5;
    if (t == 0) {
        const long long* p = (const long long*)ei;
        int ok = 1;
        for (int i = 0; i < 16; i++) { long long v = p[i]; if (v < 0 || v >= Nn) ok = 0; }
        g_ei64 = ok;
        const long long* q = (const long long*)batch;
        int ok2 = 1;
        for (int i = 0; i < 16; i++) { long long v = q[i]; if (v < 0 || v >= Bb) ok2 = 0; }
        g_batch64 = ok2;
    }
    const float* c[6] = {c0, c1, c2, c3, c4, c5};
    __shared__ float s_sum[4], s_abs[4];
    int nb = 0, ng = 0, nbe = 0;
    for (int j = 0; j < 6; j++) {
        float v = c[j][t];
        float s = v, a = fabsf(v);
        for (int o = 16; o > 0; o >>= 1) {
            s += __shfl_down_sync(0xffffffffu, s, o);
            a += __shfl_down_sync(0xffffffffu, a, o);
        }
        if (lane == 0) { s_sum[w] = s; s_abs[w] = a; }
        __syncthreads();
        if (t == 0) {
            float S = s_sum[0] + s_sum[1] + s_sum[2] + s_sum[3];
            float A = s_abs[0] + s_abs[1] + s_abs[2] + s_abs[3];
            if (A == 0.0f)      { if (nb  < 2) gp_b [nb++]  = c[j]; }
            else if (S > 64.0f) { if (ng  < 2) gp_g [ng++]  = c[j]; }
            else                { if (nbe < 2) gp_be[nbe++] = c[j]; }
        }
        __syncthreads();
    }
}

// ---------------- degree histogram + batch count (fused) ----------------
__global__ void k_deg(const void* __restrict__ ei, const void* __restrict__ batch) {
    int e = blockIdx.x * blockDim.x + threadIdx.x;
    if (e < Ee) {
        int d = ld_idx(ei, (long long)Ee + e, g_ei64);
        atomicAdd(&g_deg[d], 1);
    }
    if (e < Nn) {
        int b = ld_idx(batch, e, g_batch64);
        atomicAdd(&g_bcnt[b], 1);
    }
}

// ---------------- exclusive scan of deg -> rowstart (+dinv fused) -------------
__global__ void k_scan1() {
    __shared__ int sh[512];
    int b = blockIdx.x, t = threadIdx.x;
    int base = b * 4096 + t * 8;
    int v[8]; int tot = 0;
#pragma unroll
    for (int i = 0; i < 8; i++) {
        int idx = base + i;
        v[i] = (idx < Nn) ? g_deg[idx] : 0;
        if (idx < Nn) g_dinv[idx] = rsqrtf((float)v[i] + 1.0f);
        tot += v[i];
    }
    sh[t] = tot; __syncthreads();
    for (int off = 1; off < 512; off <<= 1) {
        int x = (t >= off) ? sh[t - off] : 0;
        __syncthreads();
        sh[t] += x;
        __syncthreads();
    }
    int run = sh[t] - tot;
#pragma unroll
    for (int i = 0; i < 8; i++) {
        int idx = base + i;
        if (idx < Nn) g_rowstart[idx] = run;
        run += v[i];
    }
    if (t == 511) g_bsum[b] = sh[511];
}

__global__ void k_scan2() {
    int run = 0;
    for (int b = 0; b < 25; b++) { int t = g_bsum[b]; g_bsum[b] = run; run += t; }
    g_rowstart[Nn] = run;
}

__global__ void k_scan3() {
    int i = blockIdx.x * blockDim.x + threadIdx.x;
    if (i < Nn) g_rowstart[i] += g_bsum[i >> 12];
}

__global__ void k_scatter(const void* __restrict__ ei) {
    int e = blockIdx.x * blockDim.x + threadIdx.x;
    if (e >= Ee) return;
    int is64 = g_ei64;
    int s = ld_idx(ei, e, is64);
    int d = ld_idx(ei, (long long)Ee + e, is64);
    int pos = g_rowstart[d] + atomicAdd(&g_cursor[d], 1);
    int2 rec;
    rec.x = s;
    rec.y = __float_as_int(g_dinv[s] * g_dinv[d]);
    g_csr[pos] = rec;
}

// ---------------- layer-1 aggregation on raw x (25 dims) ----------------------
__global__ void k_agg1(const float* __restrict__ x) {
    int warp = (blockIdx.x * blockDim.x + threadIdx.x) >> 5;
    int lane = threadIdx.x & 31;
    if (warp >= Nn) return;
    bool act = lane < FIN;
    int s = g_rowstart[warp];
    int e = g_rowstart[warp + 1];
    float acc = 0.f;
    int p = s;
    for (; p + 2 <= e; p += 2) {
        int2 r0 = g_csr[p];
        int2 r1 = g_csr[p + 1];
        float v0 = act ? __ldg(&x[r0.x * FIN + lane]) : 0.f;
        float v1 = act ? __ldg(&x[r1.x * FIN + lane]) : 0.f;
        acc = fmaf(v0, __int_as_float(r0.y), acc);
        acc = fmaf(v1, __int_as_float(r1.y), acc);
    }
    if (p < e) {
        int2 r0 = g_csr[p];
        float v0 = act ? __ldg(&x[r0.x * FIN + lane]) : 0.f;
        acc = fmaf(v0, __int_as_float(r0.y), acc);
    }
    float dd = g_dinv[warp];
    float v  = act ? x[warp * FIN + lane] : 0.f;
    acc = fmaf(v, dd * dd, acc);
    g_ax[warp * 32 + lane] = act ? acc : 0.f;
}

// -------- GEMM1: g_ax[N,25(pad32)] @ W1[25,128] + b1 -> g_h (+BN1 stats) ------
__global__ void k_gemm1(const float* __restrict__ W1) {
    __shared__ float W1s[FIN * Hh];
    __shared__ float xs[32 * 32];
    int t = threadIdx.x;              // 128
    const float* b1 = gp_b[0];
    for (int i = t; i < FIN * Hh; i += 128) W1s[i] = W1[i];
    int row0 = blockIdx.x * 32;
    for (int i = t; i < 32 * 32; i += 128) {
        int row = row0 + (i >> 5);
        xs[i] = (row < Nn) ? g_ax[row0 * 32 + i] : 0.0f;
    }
    __syncthreads();
    float bias = b1[t];
    float bs = 0.f, bss = 0.f;        // BN1 partial stats for channel t
    for (int r0 = 0; r0 < 32; r0 += 4) {
        float acc0 = 0, acc1 = 0, acc2 = 0, acc3 = 0;
#pragma unroll
        for (int k = 0; k < FIN; k++) {
            float w = W1s[k * Hh + t];
            acc0 = fmaf(xs[(r0 + 0) * 32 + k], w, acc0);
            acc1 = fmaf(xs[(r0 + 1) * 32 + k], w, acc1);
            acc2 = fmaf(xs[(r0 + 2) * 32 + k], w, acc2);
            acc3 = fmaf(xs[(r0 + 3) * 32 + k], w, acc3);
        }
        int row = row0 + r0;
        acc0 += bias; acc1 += bias; acc2 += bias; acc3 += bias;
        if (row + 0 < Nn) { g_h[(row + 0) * Hh + t] = acc0; bs += acc0; bss = fmaf(acc0, acc0, bss); }
        if (row + 1 < Nn) { g_h[(row + 1) * Hh + t] = acc1; bs += acc1; bss = fmaf(acc1, acc1, bss); }
        if (row + 2 < Nn) { g_h[(row + 2) * Hh + t] = acc2; bs += acc2; bss = fmaf(acc2, acc2, bss); }
        if (row + 3 < Nn) { g_h[(row + 3) * Hh + t] = acc3; bs += acc3; bss = fmaf(acc3, acc3, bss); }
    }
    atomicAdd(&g_bnsum[t], bs);
    atomicAdd(&g_bnsq [t], bss);
}

// ---------------- BatchNorm stats (layer 2) + coefs ----------------
__global__ void k_bnstats() {
    int c  = threadIdx.x;
    int r0 = blockIdx.x * 256;
    int re = min(r0 + 256, Nn);
    float s = 0.f, ss = 0.f;
    for (int r = r0; r < re; r++) {
        float v = g_h[r * Hh + c];
        s += v; ss = fmaf(v, v, ss);
    }
    atomicAdd(&g_bnsum[c], s);
    atomicAdd(&g_bnsq [c], ss);
}

__global__ void k_bncoef(int layer) {
    int c = threadIdx.x;
    const float* gam = gp_g[layer];
    const float* bet = gp_be[layer];
    double m   = (double)g_bnsum[c] / (double)Nn;
    double var = (double)g_bnsq[c] / (double)Nn - m * m;
    float  A   = (float)((double)gam[c] / sqrt(var + (double)EPSf));
    g_bnA[c] = A;
    g_bnB[c] = bet[c] - (float)m * A;
    g_bnsum[c] = 0.f; g_bnsq[c] = 0.f;
}

// -------- GEMM2 (tensor core): relu(bn(g_h))[fp16] @ W2[fp16] -> g_xwh --------
__global__ void __launch_bounds__(256) k_gemm2h() {
    __shared__ __half As[128][72];     // pitch 72 halves = 144B (16*9, uint4-safe)
    __shared__ __half Bs[128][72];
    __shared__ float  sA[Hh], sB[Hh];
    int t    = threadIdx.x;            // 256
    int warp = t >> 5, lane = t & 31;
    int grp  = lane >> 2, thr = lane & 3;
    int row0 = blockIdx.x * 128;
    if (t < 128) { sA[t] = g_bnA[t]; sB[t] = g_bnB[t]; }
    __syncthreads();

    float acc[16][4];
#pragma unroll
    for (int n = 0; n < 16; n++)
#pragma unroll
        for (int j = 0; j < 4; j++) acc[n][j] = 0.f;

    for (int ko = 0; ko < Hh; ko += 64) {
        {
            int r  = t >> 1;
            int c0 = (t & 1) * 32;
            int row = row0 + r;
#pragma unroll
            for (int j = 0; j < 8; j++) {
                int col = ko + c0 + j * 4;
                float4 v = make_float4(0.f, 0.f, 0.f, 0.f);
                if (row < Nn) {
                    v = *(const float4*)&g_h[row * Hh + col];
                    v.x = fmaxf(fmaf(v.x, sA[col + 0], sB[col + 0]), 0.f);
                    v.y = fmaxf(fmaf(v.y, sA[col + 1], sB[col + 1]), 0.f);
                    v.z = fmaxf(fmaf(v.z, sA[col + 2], sB[col + 2]), 0.f);
                    v.w = fmaxf(fmaf(v.w, sA[col + 3], sB[col + 3]), 0.f);
                }
                *(__half2*)&As[r][c0 + j * 4]     = __floats2half2_rn(v.x, v.y);
                *(__half2*)&As[r][c0 + j * 4 + 2] = __floats2half2_rn(v.z, v.w);
            }
        }
        {
            int n  = t >> 1;
            int c0 = (t & 1) * 32;
#pragma unroll
            for (int j = 0; j < 4; j++) {
                uint4 w = *(const uint4*)&g_W2h[n * Hh + ko + c0 + j * 8];
                *(uint4*)&Bs[n][c0 + j * 8] = w;
            }
        }
        __syncthreads();
#pragma unroll
        for (int kc = 0; kc < 4; kc++) {
            int kb = kc * 16;
            unsigned a0 = *(const unsigned*)&As[warp * 16 + grp    ][kb + thr * 2];
            unsigned a1 = *(const unsigned*)&As[warp * 16 + grp + 8][kb + thr * 2];
            unsigned a2 = *(const unsigned*)&As[warp * 16 + grp    ][kb + thr * 2 + 8];
            unsigned a3 = *(const unsigned*)&As[warp * 16 + grp + 8][kb + thr * 2 + 8];
#pragma unroll
            for (int n = 0; n < 16; n++) {
                unsigned b0 = *(const unsigned*)&Bs[n * 8 + grp][kb + thr * 2];
                unsigned b1 = *(const unsigned*)&Bs[n * 8 + grp][kb + thr * 2 + 8];
                asm volatile(
                    "mma.sync.aligned.m16n8k16.row.col.f32.f16.f16.f32 "
                    "{%0,%1,%2,%3}, {%4,%5,%6,%7}, {%8,%9}, {%0,%1,%2,%3};"
                    : "+f"(acc[n][0]), "+f"(acc[n][1]), "+f"(acc[n][2]), "+f"(acc[n][3])
                    : "r"(a0), "r"(a1), "r"(a2), "r"(a3), "r"(b0), "r"(b1));
            }
        }
        __syncthreads();
    }
    int rA = row0 + warp * 16 + grp;
    int rB = rA + 8;
#pragma unroll
    for (int n = 0; n < 16; n++) {
        int col = n * 8 + thr * 2;
        if (rA < Nn) *(__half2*)&g_xwh[rA * Hh + col] = __floats2half2_rn(acc[n][0], acc[n][1]);
        if (rB < Nn) *(__half2*)&g_xwh[rB * Hh + col] = __floats2half2_rn(acc[n][2], acc[n][3]);
    }
}

// ---------------- layer-2 aggregation (fp16 gather, warp per node) -------------
__global__ void k_agg2h() {
    int warp = (blockIdx.x * blockDim.x + threadIdx.x) >> 5;
    int lane = threadIdx.x & 31;
    if (warp >= Nn) return;
    const float* bias = gp_b[1];
    int s = g_rowstart[warp];
    int e = g_rowstart[warp + 1];
    float dd = g_dinv[warp];
    const uint2* xw2 = (const uint2*)g_xwh;
    float4 acc = make_float4(0.f, 0.f, 0.f, 0.f);
    int p = s;
    for (; p + 2 <= e; p += 2) {
        int2 r0 = g_csr[p];
        int2 r1 = g_csr[p + 1];
        uint2 raw0 = __ldg(&xw2[r0.x * 32 + lane]);
        uint2 raw1 = __ldg(&xw2[r1.x * 32 + lane]);
        float c0 = __int_as_float(r0.y), c1 = __int_as_float(r1.y);
        float2 a0 = __half22float2(*(const __half2*)&raw0.x);
        float2 a1 = __half22float2(*(const __half2*)&raw0.y);
        float2 b0 = __half22float2(*(const __half2*)&raw1.x);
        float2 b1 = __half22float2(*(const __half2*)&raw1.y);
        acc.x = fmaf(a0.x, c0, acc.x); acc.y = fmaf(a0.y, c0, acc.y);
        acc.z = fmaf(a1.x, c0, acc.z); acc.w = fmaf(a1.y, c0, acc.w);
        acc.x = fmaf(b0.x, c1, acc.x); acc.y = fmaf(b0.y, c1, acc.y);
        acc.z = fmaf(b1.x, c1, acc.z); acc.w = fmaf(b1.y, c1, acc.w);
    }
    if (p < e) {
        int2 r0 = g_csr[p];
        uint2 raw0 = __ldg(&xw2[r0.x * 32 + lane]);
        float c0 = __int_as_float(r0.y);
        float2 a0 = __half22float2(*(const __half2*)&raw0.x);
        float2 a1 = __half22float2(*(const __half2*)&raw0.y);
        acc.x = fmaf(a0.x, c0, acc.x); acc.y = fmaf(a0.y, c0, acc.y);
        acc.z = fmaf(a1.x, c0, acc.z); acc.w = fmaf(a1.y, c0, acc.w);
    }
    float sc = dd * dd;
    uint2 raw = xw2[warp * 32 + lane];
    float2 f0 = __half22float2(*(const __half2*)&raw.x);
    float2 f1 = __half22float2(*(const __half2*)&raw.y);
    acc.x = fmaf(f0.x, sc, acc.x);
    acc.y = fmaf(f0.y, sc, acc.y);
    acc.z = fmaf(f1.x, sc, acc.z);
    acc.w = fmaf(f1.y, sc, acc.w);
    float4 bv = __ldg(&((const float4*)bias)[lane]);
    acc.x += bv.x; acc.y += bv.y; acc.z += bv.z; acc.w += bv.w;
    ((float4*)g_h)[warp * 32 + lane] = acc;
}

// ---------------- batch pooling ----------------
__global__ void k_bscan() {
    __shared__ int sh[1024];
    int t = threadIdx.x;
    int base = t * 4;
    int v[4]; int tot = 0;
#pragma unroll
    for (int i = 0; i < 4; i++) { v[i] = g_bcnt[base + i]; tot += v[i]; }
    sh[t] = tot; __syncthreads();
    for (int off = 1; off < 1024; off <<= 1) {
        int x = (t >= off) ? sh[t - off] : 0;
        __syncthreads();
        sh[t] += x;
        __syncthreads();
    }
    int run = sh[t] - tot;
#pragma unroll
    for (int i = 0; i < 4; i++) { g_boff[base + i] = run; run += v[i]; }
}

__global__ void k_pool(float* __restrict__ out) {
    int g = blockIdx.x;
    int c = threadIdx.x;
    int st = g_boff[g], cn = g_bcnt[g];
    float A = g_bnA[c], Bc = g_bnB[c];
    float s = 0.f, mx = -INFINITY;
    for (int r = st; r < st + cn; r++) {
        float v = fmaxf(fmaf(g_h[r * Hh + c], A, Bc), 0.f);
        s += v;
        mx = fmaxf(mx, v);
    }
    out[g * 384 + c]       = s / (float)max(cn, 1);
    out[g * 384 + 128 + c] = (cn > 0) ? mx : 0.f;
    out[g * 384 + 256 + c] = s;
}

// ---------------- launch ----------------
extern "C" void kernel_launch(void* const* d_in, const int* in_sizes, int n_in,
                              void* d_out, int out_size) {
    const float* x  = nullptr;
    const float* W1 = nullptr;
    const float* W2 = nullptr;
    const void*  ei = nullptr;
    const void*  batch = nullptr;
    const float* v128[6] = {nullptr, nullptr, nullptr, nullptr, nullptr, nullptr};
    int n128 = 0;
    for (int i = 0; i < n_in; i++) {
        switch (in_sizes[i]) {
            case Nn * FIN:  x     = (const float*)d_in[i]; break;
            case 2 * Ee:    ei    = d_in[i];               break;
            case Nn:        batch = d_in[i];               break;
            case FIN * Hh:  W1    = (const float*)d_in[i]; break;
            case Hh * Hh:   W2    = (const float*)d_in[i]; break;
            case Hh:        if (n128 < 6) v128[n128++] = (const float*)d_in[i]; break;
        }
    }
    float* out = (float*)d_out;

    k_classify<<<1, 128>>>(ei, batch, v128[0], v128[1], v128[2],
                           v128[3], v128[4], v128[5]);
    k_setup   <<<(Nn + 255) / 256, 256>>>(W2);

    k_deg     <<<(Ee + 255) / 256, 256>>>(ei, batch);
    k_scan1   <<<25, 512>>>();
    k_scan2   <<<1, 1>>>();
    k_scan3   <<<(Nn + 255) / 256, 256>>>();
    k_scatter <<<(Ee + 255) / 256, 256>>>(ei);

    // layer 1
    k_agg1    <<<Nn / 8, 256>>>(x);
    k_gemm1   <<<(Nn + 31) / 32, 128>>>(W1);     // BN1 stats fused
    k_bncoef  <<<1, 128>>>(0);

    // layer 2
    k_gemm2h  <<<(Nn + 127) / 128, 256>>>();
    k_agg2h   <<<Nn / 8, 256>>>();
    k_bnstats <<<(Nn + 255) / 256, 128>>>();
    k_bncoef  <<<1, 128>>>(1);

    // pooling
    k_bscan   <<<1, 1024>>>();
    k_pool    <<<Bb, 128>>>(out);
}

// round 12
// speedup vs baseline: 1.0914x; 1.0914x over previous
#include <cuda_runtime.h>
#include <cuda_fp16.h>
#include <math.h>

#define Nn  100000
#define Ee  1600000
#define Bb  4096
#define FIN 25
#define Hh  128
#define EPSf 1e-5f

// ---------------- scratch (static __device__ — allocation-free) ----------------
__device__ __align__(16) float  g_h [Nn * Hh];   // h2 pre-BN (fp32)
__device__ __align__(16) __half g_xwh[Nn * Hh];  // h1 fp16, then (in-place) xw2 fp16
__device__ __align__(16) __half g_W2h[Hh * Hh];  // W2 transposed fp16: [n][k]
__device__ __align__(16) float  g_ax[Nn * 32];   // aggregated 25-dim input (padded)
__device__ int    g_deg[Nn];
__device__ int    g_cursor[Nn];
__device__ float  g_dinv[Nn];
__device__ int    g_rowstart[Nn + 1];
__device__ __align__(8) int2 g_csr[Ee];          // {src, coef as float bits}
__device__ float  g_bnsum[Hh];
__device__ float  g_bnsq [Hh];
__device__ float  g_bnA[Hh];
__device__ float  g_bnB[Hh];
__device__ int    g_bsum[64];
__device__ int    g_bcnt[Bb];
__device__ int    g_boff[Bb];

// runtime-resolved input handles
__device__ int    g_ei64;
__device__ int    g_batch64;
__device__ const float* gp_b[2];
__device__ const float* gp_g[2];
__device__ const float* gp_be[2];

__device__ __forceinline__ int ld_idx(const void* p, long long i, int is64) {
    return is64 ? (int)((const long long*)p)[i] : ((const int*)p)[i];
}

// ---------------- setup: zero scratch + convert W2 to fp16^T ----------------
__global__ void k_setup(const float* __restrict__ W2) {
    int i = blockIdx.x * blockDim.x + threadIdx.x;
    if (i < Nn) { g_deg[i] = 0; g_cursor[i] = 0; }
    if (i < Bb) g_bcnt[i] = 0;
    if (i < Hh) { g_bnsum[i] = 0.f; g_bnsq[i] = 0.f; }
    if (i < Hh * Hh) {              // i = k*128 + n
        int k = i >> 7, n = i & 127;
        g_W2h[n * Hh + k] = __float2half(W2[i]);
    }
}

// ---------------- detect index width + classify 128-vectors ----------------
__global__ void k_classify(const void* ei, const void* batch,
                           const float* c0, const float* c1, const float* c2,
                           const float* c3, const float* c4, const float* c5) {
    int t = threadIdx.x, lane = t & 31, w = t >> 5;
    if (t == 0) {
        const long long* p = (const long long*)ei;
        int ok = 1;
        for (int i = 0; i < 16; i++) { long long v = p[i]; if (v < 0 || v >= Nn) ok = 0; }
        g_ei64 = ok;
        const long long* q = (const long long*)batch;
        int ok2 = 1;
        for (int i = 0; i < 16; i++) { long long v = q[i]; if (v < 0 || v >= Bb) ok2 = 0; }
        g_batch64 = ok2;
    }
    const float* c[6] = {c0, c1, c2, c3, c4, c5};
    __shared__ float s_sum[4], s_abs[4];
    int nb = 0, ng = 0, nbe = 0;
    for (int j = 0; j < 6; j++) {
        float v = c[j][t];
        float s = v, a = fabsf(v);
        for (int o = 16; o > 0; o >>= 1) {
            s += __shfl_down_sync(0xffffffffu, s, o);
            a += __shfl_down_sync(0xffffffffu, a, o);
        }
        if (lane == 0) { s_sum[w] = s; s_abs[w] = a; }
        __syncthreads();
        if (t == 0) {
            float S = s_sum[0] + s_sum[1] + s_sum[2] + s_sum[3];
            float A = s_abs[0] + s_abs[1] + s_abs[2] + s_abs[3];
            if (A == 0.0f)      { if (nb  < 2) gp_b [nb++]  = c[j]; }
            else if (S > 64.0f) { if (ng  < 2) gp_g [ng++]  = c[j]; }
            else                { if (nbe < 2) gp_be[nbe++] = c[j]; }
        }
        __syncthreads();
    }
}

// ---------------- degree histogram + batch count ----------------
__global__ void k_deg(const void* __restrict__ ei, const void* __restrict__ batch) {
    int e = blockIdx.x * blockDim.x + threadIdx.x;
    if (e < Ee) {
        int d = ld_idx(ei, (long long)Ee + e, g_ei64);
        atomicAdd(&g_deg[d], 1);
    }
    if (e < Nn) {
        int b = ld_idx(batch, e, g_batch64);
        atomicAdd(&g_bcnt[b], 1);
    }
}

// ---------------- exclusive scan of deg -> rowstart (+dinv fused) -------------
__global__ void k_scan1() {
    __shared__ int sh[512];
    int b = blockIdx.x, t = threadIdx.x;
    int base = b * 4096 + t * 8;
    int v[8]; int tot = 0;
#pragma unroll
    for (int i = 0; i < 8; i++) {
        int idx = base + i;
        v[i] = (idx < Nn) ? g_deg[idx] : 0;
        if (idx < Nn) g_dinv[idx] = rsqrtf((float)v[i] + 1.0f);
        tot += v[i];
    }
    sh[t] = tot; __syncthreads();
    for (int off = 1; off < 512; off <<= 1) {
        int x = (t >= off) ? sh[t - off] : 0;
        __syncthreads();
        sh[t] += x;
        __syncthreads();
    }
    int run = sh[t] - tot;
#pragma unroll
    for (int i = 0; i < 8; i++) {
        int idx = base + i;
        if (idx < Nn) g_rowstart[idx] = run;
        run += v[i];
    }
    if (t == 511) g_bsum[b] = sh[511];
}

__global__ void k_scan2() {
    int run = 0;
    for (int b = 0; b < 25; b++) { int t = g_bsum[b]; g_bsum[b] = run; run += t; }
    g_rowstart[Nn] = run;
}

__global__ void k_scan3() {
    int i = blockIdx.x * blockDim.x + threadIdx.x;
    if (i < Nn) g_rowstart[i] += g_bsum[i >> 12];
}

__global__ void k_scatter(const void* __restrict__ ei) {
    int e = blockIdx.x * blockDim.x + threadIdx.x;
    if (e >= Ee) return;
    int is64 = g_ei64;
    int s = ld_idx(ei, e, is64);
    int d = ld_idx(ei, (long long)Ee + e, is64);
    int pos = g_rowstart[d] + atomicAdd(&g_cursor[d], 1);
    int2 rec;
    rec.x = s;
    rec.y = __float_as_int(g_dinv[s] * g_dinv[d]);
    g_csr[pos] = rec;
}

// ---------------- layer-1 aggregation on raw x (25 dims), 4x unroll -----------
__global__ void k_agg1(const float* __restrict__ x) {
    int warp = (blockIdx.x * blockDim.x + threadIdx.x) >> 5;
    int lane = threadIdx.x & 31;
    if (warp >= Nn) return;
    bool act = lane < FIN;
    int s = g_rowstart[warp];
    int e = g_rowstart[warp + 1];
    float acc = 0.f;
    int p = s;
    for (; p + 4 <= e; p += 4) {
        int2 r0 = g_csr[p],     r1 = g_csr[p + 1];
        int2 r2 = g_csr[p + 2], r3 = g_csr[p + 3];
        float v0 = act ? __ldg(&x[r0.x * FIN + lane]) : 0.f;
        float v1 = act ? __ldg(&x[r1.x * FIN + lane]) : 0.f;
        float v2 = act ? __ldg(&x[r2.x * FIN + lane]) : 0.f;
        float v3 = act ? __ldg(&x[r3.x * FIN + lane]) : 0.f;
        acc = fmaf(v0, __int_as_float(r0.y), acc);
        acc = fmaf(v1, __int_as_float(r1.y), acc);
        acc = fmaf(v2, __int_as_float(r2.y), acc);
        acc = fmaf(v3, __int_as_float(r3.y), acc);
    }
    for (; p < e; p++) {
        int2 r0 = g_csr[p];
        float v0 = act ? __ldg(&x[r0.x * FIN + lane]) : 0.f;
        acc = fmaf(v0, __int_as_float(r0.y), acc);
    }
    float dd = g_dinv[warp];
    float v  = act ? x[warp * FIN + lane] : 0.f;
    acc = fmaf(v, dd * dd, acc);
    g_ax[warp * 32 + lane] = act ? acc : 0.f;
}

// -- GEMM1: g_ax @ W1 + b1 -> h1 (fp16, into g_xwh) + BN1 stats (fp32 exact) ---
__global__ void k_gemm1(const float* __restrict__ W1) {
    __shared__ float W1s[FIN * Hh];
    __shared__ float xs[32 * 32];
    int t = threadIdx.x;              // 128
    const float* b1 = gp_b[0];
    for (int i = t; i < FIN * Hh; i += 128) W1s[i] = W1[i];
    int row0 = blockIdx.x * 32;
    for (int i = t; i < 32 * 32; i += 128) {
        int row = row0 + (i >> 5);
        xs[i] = (row < Nn) ? g_ax[row0 * 32 + i] : 0.0f;
    }
    __syncthreads();
    float bias = b1[t];
    float bs = 0.f, bss = 0.f;
    for (int r0 = 0; r0 < 32; r0 += 4) {
        float acc0 = 0, acc1 = 0, acc2 = 0, acc3 = 0;
#pragma unroll
        for (int k = 0; k < FIN; k++) {
            float w = W1s[k * Hh + t];
            acc0 = fmaf(xs[(r0 + 0) * 32 + k], w, acc0);
            acc1 = fmaf(xs[(r0 + 1) * 32 + k], w, acc1);
            acc2 = fmaf(xs[(r0 + 2) * 32 + k], w, acc2);
            acc3 = fmaf(xs[(r0 + 3) * 32 + k], w, acc3);
        }
        int row = row0 + r0;
        acc0 += bias; acc1 += bias; acc2 += bias; acc3 += bias;
        if (row + 0 < Nn) { g_xwh[(row + 0) * Hh + t] = __float2half(acc0); bs += acc0; bss = fmaf(acc0, acc0, bss); }
        if (row + 1 < Nn) { g_xwh[(row + 1) * Hh + t] = __float2half(acc1); bs += acc1; bss = fmaf(acc1, acc1, bss); }
        if (row + 2 < Nn) { g_xwh[(row + 2) * Hh + t] = __float2half(acc2); bs += acc2; bss = fmaf(acc2, acc2, bss); }
        if (row + 3 < Nn) { g_xwh[(row + 3) * Hh + t] = __float2half(acc3); bs += acc3; bss = fmaf(acc3, acc3, bss); }
    }
    atomicAdd(&g_bnsum[t], bs);
    atomicAdd(&g_bnsq [t], bss);
}

__global__ void k_bncoef(int layer) {
    int c = threadIdx.x;
    const float* gam = gp_g[layer];
    const float* bet = gp_be[layer];
    double m   = (double)g_bnsum[c] / (double)Nn;
    double var = (double)g_bnsq[c] / (double)Nn - m * m;
    float  A   = (float)((double)gam[c] / sqrt(var + (double)EPSf));
    g_bnA[c] = A;
    g_bnB[c] = bet[c] - (float)m * A;
    g_bnsum[c] = 0.f; g_bnsq[c] = 0.f;   // reset for layer-2 stats
}

// -- GEMM2 (HMMA): relu(bn(h1_fp16)) @ W2 -> xw2 fp16 IN-PLACE into g_xwh ------
// Each block owns rows [row0,row0+128): reads its h1 rows, writes same rows.
__global__ void __launch_bounds__(256) k_gemm2h() {
    __shared__ __half As[128][72];     // pitch 72 halves = 144B (16*9, uint4-safe)
    __shared__ __half Bs[128][72];
    __shared__ float  sA[Hh], sB[Hh];
    int t    = threadIdx.x;            // 256
    int warp = t >> 5, lane = t & 31;
    int grp  = lane >> 2, thr = lane & 3;
    int row0 = blockIdx.x * 128;
    if (t < 128) { sA[t] = g_bnA[t]; sB[t] = g_bnB[t]; }
    __syncthreads();

    float acc[16][4];
#pragma unroll
    for (int n = 0; n < 16; n++)
#pragma unroll
        for (int j = 0; j < 4; j++) acc[n][j] = 0.f;

    for (int ko = 0; ko < Hh; ko += 64) {
        {   // A: 128 rows x 64 k, fp16 load + BN + ReLU + re-round
            int r  = t >> 1;
            int c0 = (t & 1) * 32;
            int row = row0 + r;
#pragma unroll
            for (int j = 0; j < 8; j++) {
                int col = ko + c0 + j * 4;
                float2 f0 = make_float2(0.f, 0.f), f1 = make_float2(0.f, 0.f);
                if (row < Nn) {
                    uint2 raw = *(const uint2*)&g_xwh[row * Hh + col];
                    f0 = __half22float2(*(const __half2*)&raw.x);
                    f1 = __half22float2(*(const __half2*)&raw.y);
                    f0.x = fmaxf(fmaf(f0.x, sA[col + 0], sB[col + 0]), 0.f);
                    f0.y = fmaxf(fmaf(f0.y, sA[col + 1], sB[col + 1]), 0.f);
                    f1.x = fmaxf(fmaf(f1.x, sA[col + 2], sB[col + 2]), 0.f);
                    f1.y = fmaxf(fmaf(f1.y, sA[col + 3], sB[col + 3]), 0.f);
                }
                *(__half2*)&As[r][c0 + j * 4]     = __floats2half2_rn(f0.x, f0.y);
                *(__half2*)&As[r][c0 + j * 4 + 2] = __floats2half2_rn(f1.x, f1.y);
            }
        }
        {   // B: 128 n x 64 k
            int n  = t >> 1;
            int c0 = (t & 1) * 32;
#pragma unroll
            for (int j = 0; j < 4; j++) {
                uint4 w = *(const uint4*)&g_W2h[n * Hh + ko + c0 + j * 8];
                *(uint4*)&Bs[n][c0 + j * 8] = w;
            }
        }
        __syncthreads();
#pragma unroll
        for (int kc = 0; kc < 4; kc++) {
            int kb = kc * 16;
            unsigned a0 = *(const unsigned*)&As[warp * 16 + grp    ][kb + thr * 2];
            unsigned a1 = *(const unsigned*)&As[warp * 16 + grp + 8][kb + thr * 2];
            unsigned a2 = *(const unsigned*)&As[warp * 16 + grp    ][kb + thr * 2 + 8];
            unsigned a3 = *(const unsigned*)&As[warp * 16 + grp + 8][kb + thr * 2 + 8];
#pragma unroll
            for (int n = 0; n < 16; n++) {
                unsigned b0 = *(const unsigned*)&Bs[n * 8 + grp][kb + thr * 2];
                unsigned b1 = *(const unsigned*)&Bs[n * 8 + grp][kb + thr * 2 + 8];
                asm volatile(
                    "mma.sync.aligned.m16n8k16.row.col.f32.f16.f16.f32 "
                    "{%0,%1,%2,%3}, {%4,%5,%6,%7}, {%8,%9}, {%0,%1,%2,%3};"
                    : "+f"(acc[n][0]), "+f"(acc[n][1]), "+f"(acc[n][2]), "+f"(acc[n][3])
                    : "r"(a0), "r"(a1), "r"(a2), "r"(a3), "r"(b0), "r"(b1));
            }
        }
        __syncthreads();
    }
    int rA = row0 + warp * 16 + grp;
    int rB = rA + 8;
#pragma unroll
    for (int n = 0; n < 16; n++) {
        int col = n * 8 + thr * 2;
        if (rA < Nn) *(__half2*)&g_xwh[rA * Hh + col] = __floats2half2_rn(acc[n][0], acc[n][1]);
        if (rB < Nn) *(__half2*)&g_xwh[rB * Hh + col] = __floats2half2_rn(acc[n][2], acc[n][3]);
    }
}

// -- layer-2 aggregation: 8 nodes/warp, 4x unroll, fused BN2 stats -------------
__global__ void __launch_bounds__(256) k_agg2h() {
    __shared__ float s_sum[Hh], s_sq[Hh];
    int t = threadIdx.x;
    if (t < Hh) { s_sum[t] = 0.f; s_sq[t] = 0.f; }
    __syncthreads();
    int lane = t & 31;
    int node0 = ((blockIdx.x * blockDim.x + t) >> 5) * 8;
    const float* bias = gp_b[1];
    float4 bv = __ldg(&((const float4*)bias)[lane]);
    const uint2* xw2 = (const uint2*)g_xwh;
    float ls0 = 0.f, ls1 = 0.f, ls2 = 0.f, ls3 = 0.f;
    float lq0 = 0.f, lq1 = 0.f, lq2 = 0.f, lq3 = 0.f;

    for (int ni = 0; ni < 8; ni++) {
        int node = node0 + ni;
        if (node >= Nn) break;
        int s = g_rowstart[node];
        int e = g_rowstart[node + 1];
        float4 acc = make_float4(0.f, 0.f, 0.f, 0.f);
        int p = s;
        for (; p + 4 <= e; p += 4) {
            int2 r0 = g_csr[p],     r1 = g_csr[p + 1];
            int2 r2 = g_csr[p + 2], r3 = g_csr[p + 3];
            uint2 w0 = __ldg(&xw2[r0.x * 32 + lane]);
            uint2 w1 = __ldg(&xw2[r1.x * 32 + lane]);
            uint2 w2 = __ldg(&xw2[r2.x * 32 + lane]);
            uint2 w3 = __ldg(&xw2[r3.x * 32 + lane]);
            float c0 = __int_as_float(r0.y), c1 = __int_as_float(r1.y);
            float c2 = __int_as_float(r2.y), c3 = __int_as_float(r3.y);
            float2 p0, p1;
            p0 = __half22float2(*(const __half2*)&w0.x); p1 = __half22float2(*(const __half2*)&w0.y);
            acc.x = fmaf(p0.x, c0, acc.x); acc.y = fmaf(p0.y, c0, acc.y);
            acc.z = fmaf(p1.x, c0, acc.z); acc.w = fmaf(p1.y, c0, acc.w);
            p0 = __half22float2(*(const __half2*)&w1.x); p1 = __half22float2(*(const __half2*)&w1.y);
            acc.x = fmaf(p0.x, c1, acc.x); acc.y = fmaf(p0.y, c1, acc.y);
            acc.z = fmaf(p1.x, c1, acc.z); acc.w = fmaf(p1.y, c1, acc.w);
            p0 = __half22float2(*(const __half2*)&w2.x); p1 = __half22float2(*(const __half2*)&w2.y);
            acc.x = fmaf(p0.x, c2, acc.x); acc.y = fmaf(p0.y, c2, acc.y);
            acc.z = fmaf(p1.x, c2, acc.z); acc.w = fmaf(p1.y, c2, acc.w);
            p0 = __half22float2(*(const __half2*)&w3.x); p1 = __half22float2(*(const __half2*)&w3.y);
            acc.x = fmaf(p0.x, c3, acc.x); acc.y = fmaf(p0.y, c3, acc.y);
            acc.z = fmaf(p1.x, c3, acc.z); acc.w = fmaf(p1.y, c3, acc.w);
        }
        for (; p < e; p++) {
            int2 r0 = g_csr[p];
            uint2 w0 = __ldg(&xw2[r0.x * 32 + lane]);
            float c0 = __int_as_float(r0.y);
            float2 p0 = __half22float2(*(const __half2*)&w0.x);
            float2 p1 = __half22float2(*(const __half2*)&w0.y);
            acc.x = fmaf(p0.x, c0, acc.x); acc.y = fmaf(p0.y, c0, acc.y);
            acc.z = fmaf(p1.x, c0, acc.z); acc.w = fmaf(p1.y, c0, acc.w);
        }
        float dd = g_dinv[node];
        float sc = dd * dd;
        uint2 wr = xw2[node * 32 + lane];
        float2 f0 = __half22float2(*(const __half2*)&wr.x);
        float2 f1 = __half22float2(*(const __half2*)&wr.y);
        acc.x = fmaf(f0.x, sc, acc.x) + bv.x;
        acc.y = fmaf(f0.y, sc, acc.y) + bv.y;
        acc.z = fmaf(f1.x, sc, acc.z) + bv.z;
        acc.w = fmaf(f1.y, sc, acc.w) + bv.w;
        ((float4*)g_h)[node * 32 + lane] = acc;
        ls0 += acc.x; lq0 = fmaf(acc.x, acc.x, lq0);
        ls1 += acc.y; lq1 = fmaf(acc.y, acc.y, lq1);
        ls2 += acc.z; lq2 = fmaf(acc.z, acc.z, lq2);
        ls3 += acc.w; lq3 = fmaf(acc.w, acc.w, lq3);
    }
    atomicAdd(&s_sum[lane * 4 + 0], ls0); atomicAdd(&s_sq[lane * 4 + 0], lq0);
    atomicAdd(&s_sum[lane * 4 + 1], ls1); atomicAdd(&s_sq[lane * 4 + 1], lq1);
    atomicAdd(&s_sum[lane * 4 + 2], ls2); atomicAdd(&s_sq[lane * 4 + 2], lq2);
    atomicAdd(&s_sum[lane * 4 + 3], ls3); atomicAdd(&s_sq[lane * 4 + 3], lq3);
    __syncthreads();
    if (t < Hh) {
        atomicAdd(&g_bnsum[t], s_sum[t]);
        atomicAdd(&g_bnsq [t], s_sq[t]);
    }
}

// ---------------- batch pooling ----------------
__global__ void k_bscan() {
    __shared__ int sh[1024];
    int t = threadIdx.x;
    int base = t * 4;
    int v[4]; int tot = 0;
#pragma unroll
    for (int i = 0; i < 4; i++) { v[i] = g_bcnt[base + i]; tot += v[i]; }
    sh[t] = tot; __syncthreads();
    for (int off = 1; off < 1024; off <<= 1) {
        int x = (t >= off) ? sh[t - off] : 0;
        __syncthreads();
        sh[t] += x;
        __syncthreads();
    }
    int run = sh[t] - tot;
#pragma unroll
    for (int i = 0; i < 4; i++) { g_boff[base + i] = run; run += v[i]; }
}

__global__ void k_pool(float* __restrict__ out) {
    int g = blockIdx.x;
    int c = threadIdx.x;
    int st = g_boff[g], cn = g_bcnt[g];
    float A = g_bnA[c], Bc = g_bnB[c];
    float s = 0.f, mx = -INFINITY;
    for (int r = st; r < st + cn; r++) {
        float v = fmaxf(fmaf(g_h[r * Hh + c], A, Bc), 0.f);
        s += v;
        mx = fmaxf(mx, v);
    }
    out[g * 384 + c]       = s / (float)max(cn, 1);
    out[g * 384 + 128 + c] = (cn > 0) ? mx : 0.f;
    out[g * 384 + 256 + c] = s;
}

// ---------------- launch ----------------
extern "C" void kernel_launch(void* const* d_in, const int* in_sizes, int n_in,
                              void* d_out, int out_size) {
    const float* x  = nullptr;
    const float* W1 = nullptr;
    const float* W2 = nullptr;
    const void*  ei = nullptr;
    const void*  batch = nullptr;
    const float* v128[6] = {nullptr, nullptr, nullptr, nullptr, nullptr, nullptr};
    int n128 = 0;
    for (int i = 0; i < n_in; i++) {
        switch (in_sizes[i]) {
            case Nn * FIN:  x     = (const float*)d_in[i]; break;
            case 2 * Ee:    ei    = d_in[i];               break;
            case Nn:        batch = d_in[i];               break;
            case FIN * Hh:  W1    = (const float*)d_in[i]; break;
            case Hh * Hh:   W2    = (const float*)d_in[i]; break;
            case Hh:        if (n128 < 6) v128[n128++] = (const float*)d_in[i]; break;
        }
    }
    float* out = (float*)d_out;

    k_classify<<<1, 128>>>(ei, batch, v128[0], v128[1], v128[2],
                           v128[3], v128[4], v128[5]);
    k_setup   <<<(Nn + 255) / 256, 256>>>(W2);

    k_deg     <<<(Ee + 255) / 256, 256>>>(ei, batch);
    k_scan1   <<<25, 512>>>();
    k_scan2   <<<1, 1>>>();
    k_scan3   <<<(Nn + 255) / 256, 256>>>();
    k_scatter <<<(Ee + 255) / 256, 256>>>(ei);

    // layer 1
    k_agg1    <<<Nn / 8, 256>>>(x);
    k_gemm1   <<<(Nn + 31) / 32, 128>>>(W1);      // h1 fp16 + BN1 stats fused
    k_bncoef  <<<1, 128>>>(0);

    // layer 2
    k_gemm2h  <<<(Nn + 127) / 128, 256>>>();      // in-place h1 -> xw2 (fp16)
    k_agg2h   <<<(Nn + 63) / 64, 256>>>();        // 8 nodes/warp + BN2 stats fused
    k_bncoef  <<<1, 128>>>(1);

    // pooling
    k_bscan   <<<1, 1024>>>();
    k_pool    <<<Bb, 128>>>(out);
}

// round 13
// speedup vs baseline: 1.1006x; 1.0085x over previous
#include <cuda_runtime.h>
#include <cuda_fp16.h>
#include <math.h>

#define Nn  100000
#define Ee  1600000
#define Bb  4096
#define FIN 25
#define Hh  128
#define EPSf 1e-5f

// ---------------- scratch (static __device__ — allocation-free) ----------------
__device__ __align__(16) float  g_h [Nn * Hh];   // h2 pre-BN (fp32)
__device__ __align__(16) __half g_xwh[Nn * Hh];  // h1 fp16, then (in-place) xw2 fp16
__device__ __align__(16) __half g_W2h[Hh * Hh];  // W2 transposed fp16: [n][k]
__device__ __align__(16) float  g_ax[Nn * 32];   // aggregated 25-dim input (padded)
__device__ int    g_deg[Nn];
__device__ int    g_cursor[Nn];
__device__ float  g_dinv[Nn];
__device__ int    g_rowstart[Nn + 1];
__device__ __align__(8) int2 g_csr[Ee];          // {src, coef as float bits}
__device__ float  g_bnsum[Hh];
__device__ float  g_bnsq [Hh];
__device__ float  g_bnA[Hh];
__device__ float  g_bnB[Hh];
__device__ int    g_bsum[64];
__device__ int    g_bcnt[Bb];
__device__ int    g_boff[Bb];

// runtime-resolved input handles
__device__ int    g_ei64;
__device__ int    g_batch64;
__device__ const float* gp_b[2];
__device__ const float* gp_g[2];
__device__ const float* gp_be[2];

__device__ __forceinline__ int ld_idx(const void* p, long long i, int is64) {
    return is64 ? (int)((const long long*)p)[i] : ((const int*)p)[i];
}

// ---------------- setup: zero scratch + convert W2 to fp16^T ----------------
__global__ void k_setup(const float* __restrict__ W2) {
    int i = blockIdx.x * blockDim.x + threadIdx.x;
    if (i < Nn) { g_deg[i] = 0; g_cursor[i] = 0; }
    if (i < Bb) g_bcnt[i] = 0;
    if (i < Hh) { g_bnsum[i] = 0.f; g_bnsq[i] = 0.f; }
    if (i < Hh * Hh) {              // i = k*128 + n
        int k = i >> 7, n = i & 127;
        g_W2h[n * Hh + k] = __float2half(W2[i]);
    }
}

// ---------------- detect index width + classify 128-vectors ----------------
__global__ void k_classify(const void* ei, const void* batch,
                           const float* c0, const float* c1, const float* c2,
                           const float* c3, const float* c4, const float* c5) {
    int t = threadIdx.x, lane = t & 31, w = t >> 5;
    if (t == 0) {
        const long long* p = (const long long*)ei;
        int ok = 1;
        for (int i = 0; i < 16; i++) { long long v = p[i]; if (v < 0 || v >= Nn) ok = 0; }
        g_ei64 = ok;
        const long long* q = (const long long*)batch;
        int ok2 = 1;
        for (int i = 0; i < 16; i++) { long long v = q[i]; if (v < 0 || v >= Bb) ok2 = 0; }
        g_batch64 = ok2;
    }
    const float* c[6] = {c0, c1, c2, c3, c4, c5};
    __shared__ float s_sum[4], s_abs[4];
    int nb = 0, ng = 0, nbe = 0;
    for (int j = 0; j < 6; j++) {
        float v = c[j][t];
        float s = v, a = fabsf(v);
        for (int o = 16; o > 0; o >>= 1) {
            s += __shfl_down_sync(0xffffffffu, s, o);
            a += __shfl_down_sync(0xffffffffu, a, o);
        }
        if (lane == 0) { s_sum[w] = s; s_abs[w] = a; }
        __syncthreads();
        if (t == 0) {
            float S = s_sum[0] + s_sum[1] + s_sum[2] + s_sum[3];
            float A = s_abs[0] + s_abs[1] + s_abs[2] + s_abs[3];
            if (A == 0.0f)      { if (nb  < 2) gp_b [nb++]  = c[j]; }
            else if (S > 64.0f) { if (ng  < 2) gp_g [ng++]  = c[j]; }
            else                { if (nbe < 2) gp_be[nbe++] = c[j]; }
        }
        __syncthreads();
    }
}

// ---------------- degree histogram + batch count ----------------
__global__ void k_deg(const void* __restrict__ ei, const void* __restrict__ batch) {
    int e = blockIdx.x * blockDim.x + threadIdx.x;
    if (e < Ee) {
        int d = ld_idx(ei, (long long)Ee + e, g_ei64);
        atomicAdd(&g_deg[d], 1);
    }
    if (e < Nn) {
        int b = ld_idx(batch, e, g_batch64);
        atomicAdd(&g_bcnt[b], 1);
    }
}

// ---------------- exclusive scan of deg -> rowstart (+dinv fused) -------------
__global__ void k_scan1() {
    __shared__ int sh[512];
    int b = blockIdx.x, t = threadIdx.x;
    int base = b * 4096 + t * 8;
    int v[8]; int tot = 0;
#pragma unroll
    for (int i = 0; i < 8; i++) {
        int idx = base + i;
        v[i] = (idx < Nn) ? g_deg[idx] : 0;
        if (idx < Nn) g_dinv[idx] = rsqrtf((float)v[i] + 1.0f);
        tot += v[i];
    }
    sh[t] = tot; __syncthreads();
    for (int off = 1; off < 512; off <<= 1) {
        int x = (t >= off) ? sh[t - off] : 0;
        __syncthreads();
        sh[t] += x;
        __syncthreads();
    }
    int run = sh[t] - tot;
#pragma unroll
    for (int i = 0; i < 8; i++) {
        int idx = base + i;
        if (idx < Nn) g_rowstart[idx] = run;
        run += v[i];
    }
    if (t == 511) g_bsum[b] = sh[511];
}

__global__ void k_scan2() {
    int run = 0;
    for (int b = 0; b < 25; b++) { int t = g_bsum[b]; g_bsum[b] = run; run += t; }
    g_rowstart[Nn] = run;
}

__global__ void k_scan3() {
    int i = blockIdx.x * blockDim.x + threadIdx.x;
    if (i < Nn) g_rowstart[i] += g_bsum[i >> 12];
}

__global__ void k_scatter(const void* __restrict__ ei) {
    int e = blockIdx.x * blockDim.x + threadIdx.x;
    if (e >= Ee) return;
    int is64 = g_ei64;
    int s = ld_idx(ei, e, is64);
    int d = ld_idx(ei, (long long)Ee + e, is64);
    int pos = g_rowstart[d] + atomicAdd(&g_cursor[d], 1);
    int2 rec;
    rec.x = s;
    rec.y = __float_as_int(g_dinv[s] * g_dinv[d]);
    g_csr[pos] = rec;
}

// ---------------- layer-1 aggregation on raw x (25 dims), 4x unroll -----------
__global__ void k_agg1(const float* __restrict__ x) {
    int warp = (blockIdx.x * blockDim.x + threadIdx.x) >> 5;
    int lane = threadIdx.x & 31;
    if (warp >= Nn) return;
    bool act = lane < FIN;
    int s = g_rowstart[warp];
    int e = g_rowstart[warp + 1];
    float acc = 0.f;
    int p = s;
    for (; p + 4 <= e; p += 4) {
        int2 r0 = g_csr[p],     r1 = g_csr[p + 1];
        int2 r2 = g_csr[p + 2], r3 = g_csr[p + 3];
        float v0 = act ? __ldg(&x[r0.x * FIN + lane]) : 0.f;
        float v1 = act ? __ldg(&x[r1.x * FIN + lane]) : 0.f;
        float v2 = act ? __ldg(&x[r2.x * FIN + lane]) : 0.f;
        float v3 = act ? __ldg(&x[r3.x * FIN + lane]) : 0.f;
        acc = fmaf(v0, __int_as_float(r0.y), acc);
        acc = fmaf(v1, __int_as_float(r1.y), acc);
        acc = fmaf(v2, __int_as_float(r2.y), acc);
        acc = fmaf(v3, __int_as_float(r3.y), acc);
    }
    for (; p < e; p++) {
        int2 r0 = g_csr[p];
        float v0 = act ? __ldg(&x[r0.x * FIN + lane]) : 0.f;
        acc = fmaf(v0, __int_as_float(r0.y), acc);
    }
    float dd = g_dinv[warp];
    float v  = act ? x[warp * FIN + lane] : 0.f;
    acc = fmaf(v, dd * dd, acc);
    g_ax[warp * 32 + lane] = act ? acc : 0.f;
}

// -- GEMM1: g_ax @ W1 + b1 -> h1 (fp16, into g_xwh) + BN1 stats (fp32 exact) ---
__global__ void k_gemm1(const float* __restrict__ W1) {
    __shared__ float W1s[FIN * Hh];
    __shared__ float xs[32 * 32];
    int t = threadIdx.x;              // 128
    const float* b1 = gp_b[0];
    for (int i = t; i < FIN * Hh; i += 128) W1s[i] = W1[i];
    int row0 = blockIdx.x * 32;
    for (int i = t; i < 32 * 32; i += 128) {
        int row = row0 + (i >> 5);
        xs[i] = (row < Nn) ? g_ax[row0 * 32 + i] : 0.0f;
    }
    __syncthreads();
    float bias = b1[t];
    float bs = 0.f, bss = 0.f;
    for (int r0 = 0; r0 < 32; r0 += 4) {
        float acc0 = 0, acc1 = 0, acc2 = 0, acc3 = 0;
#pragma unroll
        for (int k = 0; k < FIN; k++) {
            float w = W1s[k * Hh + t];
            acc0 = fmaf(xs[(r0 + 0) * 32 + k], w, acc0);
            acc1 = fmaf(xs[(r0 + 1) * 32 + k], w, acc1);
            acc2 = fmaf(xs[(r0 + 2) * 32 + k], w, acc2);
            acc3 = fmaf(xs[(r0 + 3) * 32 + k], w, acc3);
        }
        int row = row0 + r0;
        acc0 += bias; acc1 += bias; acc2 += bias; acc3 += bias;
        if (row + 0 < Nn) { g_xwh[(row + 0) * Hh + t] = __float2half(acc0); bs += acc0; bss = fmaf(acc0, acc0, bss); }
        if (row + 1 < Nn) { g_xwh[(row + 1) * Hh + t] = __float2half(acc1); bs += acc1; bss = fmaf(acc1, acc1, bss); }
        if (row + 2 < Nn) { g_xwh[(row + 2) * Hh + t] = __float2half(acc2); bs += acc2; bss = fmaf(acc2, acc2, bss); }
        if (row + 3 < Nn) { g_xwh[(row + 3) * Hh + t] = __float2half(acc3); bs += acc3; bss = fmaf(acc3, acc3, bss); }
    }
    atomicAdd(&g_bnsum[t], bs);
    atomicAdd(&g_bnsq [t], bss);
}

__global__ void k_bncoef(int layer) {
    int c = threadIdx.x;
    const float* gam = gp_g[layer];
    const float* bet = gp_be[layer];
    double m   = (double)g_bnsum[c] / (double)Nn;
    double var = (double)g_bnsq[c] / (double)Nn - m * m;
    float  A   = (float)((double)gam[c] / sqrt(var + (double)EPSf));
    g_bnA[c] = A;
    g_bnB[c] = bet[c] - (float)m * A;
    g_bnsum[c] = 0.f; g_bnsq[c] = 0.f;   // reset for layer-2 stats
}

// -- GEMM2 (HMMA): relu(bn(h1_fp16)) @ W2 -> xw2 fp16 IN-PLACE into g_xwh ------
// Each block owns rows [row0,row0+128): reads its h1 rows, writes same rows.
__global__ void __launch_bounds__(256) k_gemm2h() {
    __shared__ __half As[128][72];     // pitch 72 halves = 144B (16*9, uint4-safe)
    __shared__ __half Bs[128][72];
    __shared__ float  sA[Hh], sB[Hh];
    int t    = threadIdx.x;            // 256
    int warp = t >> 5, lane = t & 31;
    int grp  = lane >> 2, thr = lane & 3;
    int row0 = blockIdx.x * 128;
    if (t < 128) { sA[t] = g_bnA[t]; sB[t] = g_bnB[t]; }
    __syncthreads();

    float acc[16][4];
#pragma unroll
    for (int n = 0; n < 16; n++)
#pragma unroll
        for (int j = 0; j < 4; j++) acc[n][j] = 0.f;

    for (int ko = 0; ko < Hh; ko += 64) {
        {   // A: 128 rows x 64 k, fp16 load + BN + ReLU + re-round
            int r  = t >> 1;
            int c0 = (t & 1) * 32;
            int row = row0 + r;
#pragma unroll
            for (int j = 0; j < 8; j++) {
                int col = ko + c0 + j * 4;
                float2 f0 = make_float2(0.f, 0.f), f1 = make_float2(0.f, 0.f);
                if (row < Nn) {
                    uint2 raw = *(const uint2*)&g_xwh[row * Hh + col];
                    f0 = __half22float2(*(const __half2*)&raw.x);
                    f1 = __half22float2(*(const __half2*)&raw.y);
                    f0.x = fmaxf(fmaf(f0.x, sA[col + 0], sB[col + 0]), 0.f);
                    f0.y = fmaxf(fmaf(f0.y, sA[col + 1], sB[col + 1]), 0.f);
                    f1.x = fmaxf(fmaf(f1.x, sA[col + 2], sB[col + 2]), 0.f);
                    f1.y = fmaxf(fmaf(f1.y, sA[col + 3], sB[col + 3]), 0.f);
                }
                *(__half2*)&As[r][c0 + j * 4]     = __floats2half2_rn(f0.x, f0.y);
                *(__half2*)&As[r][c0 + j * 4 + 2] = __floats2half2_rn(f1.x, f1.y);
            }
        }
        {   // B: 128 n x 64 k
            int n  = t >> 1;
            int c0 = (t & 1) * 32;
#pragma unroll
            for (int j = 0; j < 4; j++) {
                uint4 w = *(const uint4*)&g_W2h[n * Hh + ko + c0 + j * 8];
                *(uint4*)&Bs[n][c0 + j * 8] = w;
            }
        }
        __syncthreads();
#pragma unroll
        for (int kc = 0; kc < 4; kc++) {
            int kb = kc * 16;
            unsigned a0 = *(const unsigned*)&As[warp * 16 + grp    ][kb + thr * 2];
            unsigned a1 = *(const unsigned*)&As[warp * 16 + grp + 8][kb + thr * 2];
            unsigned a2 = *(const unsigned*)&As[warp * 16 + grp    ][kb + thr * 2 + 8];
            unsigned a3 = *(const unsigned*)&As[warp * 16 + grp + 8][kb + thr * 2 + 8];
#pragma unroll
            for (int n = 0; n < 16; n++) {
                unsigned b0 = *(const unsigned*)&Bs[n * 8 + grp][kb + thr * 2];
                unsigned b1 = *(const unsigned*)&Bs[n * 8 + grp][kb + thr * 2 + 8];
                asm volatile(
                    "mma.sync.aligned.m16n8k16.row.col.f32.f16.f16.f32 "
                    "{%0,%1,%2,%3}, {%4,%5,%6,%7}, {%8,%9}, {%0,%1,%2,%3};"
                    : "+f"(acc[n][0]), "+f"(acc[n][1]), "+f"(acc[n][2]), "+f"(acc[n][3])
                    : "r"(a0), "r"(a1), "r"(a2), "r"(a3), "r"(b0), "r"(b1));
            }
        }
        __syncthreads();
    }
    int rA = row0 + warp * 16 + grp;
    int rB = rA + 8;
#pragma unroll
    for (int n = 0; n < 16; n++) {
        int col = n * 8 + thr * 2;
        if (rA < Nn) *(__half2*)&g_xwh[rA * Hh + col] = __floats2half2_rn(acc[n][0], acc[n][1]);
        if (rB < Nn) *(__half2*)&g_xwh[rB * Hh + col] = __floats2half2_rn(acc[n][2], acc[n][3]);
    }
}

// -- layer-2 aggregation: 8 nodes/warp, 4x unroll, fused BN2 stats -------------
__global__ void __launch_bounds__(256) k_agg2h() {
    __shared__ float s_sum[Hh], s_sq[Hh];
    int t = threadIdx.x;
    if (t < Hh) { s_sum[t] = 0.f; s_sq[t] = 0.f; }
    __syncthreads();
    int lane = t & 31;
    int node0 = ((blockIdx.x * blockDim.x + t) >> 5) * 8;
    const float* bias = gp_b[1];
    float4 bv = __ldg(&((const float4*)bias)[lane]);
    const uint2* xw2 = (const uint2*)g_xwh;
    float ls0 = 0.f, ls1 = 0.f, ls2 = 0.f, ls3 = 0.f;
    float lq0 = 0.f, lq1 = 0.f, lq2 = 0.f, lq3 = 0.f;

    for (int ni = 0; ni < 8; ni++) {
        int node = node0 + ni;
        if (node >= Nn) break;
        int s = g_rowstart[node];
        int e = g_rowstart[node + 1];
        float4 acc = make_float4(0.f, 0.f, 0.f, 0.f);
        int p = s;
        for (; p + 4 <= e; p += 4) {
            int2 r0 = g_csr[p],     r1 = g_csr[p + 1];
            int2 r2 = g_csr[p + 2], r3 = g_csr[p + 3];
            uint2 w0 = __ldg(&xw2[r0.x * 32 + lane]);
            uint2 w1 = __ldg(&xw2[r1.x * 32 + lane]);
            uint2 w2 = __ldg(&xw2[r2.x * 32 + lane]);
            uint2 w3 = __ldg(&xw2[r3.x * 32 + lane]);
            float c0 = __int_as_float(r0.y), c1 = __int_as_float(r1.y);
            float c2 = __int_as_float(r2.y), c3 = __int_as_float(r3.y);
            float2 p0, p1;
            p0 = __half22float2(*(const __half2*)&w0.x); p1 = __half22float2(*(const __half2*)&w0.y);
            acc.x = fmaf(p0.x, c0, acc.x); acc.y = fmaf(p0.y, c0, acc.y);
            acc.z = fmaf(p1.x, c0, acc.z); acc.w = fmaf(p1.y, c0, acc.w);
            p0 = __half22float2(*(const __half2*)&w1.x); p1 = __half22float2(*(const __half2*)&w1.y);
            acc.x = fmaf(p0.x, c1, acc.x); acc.y = fmaf(p0.y, c1, acc.y);
            acc.z = fmaf(p1.x, c1, acc.z); acc.w = fmaf(p1.y, c1, acc.w);
            p0 = __half22float2(*(const __half2*)&w2.x); p1 = __half22float2(*(const __half2*)&w2.y);
            acc.x = fmaf(p0.x, c2, acc.x); acc.y = fmaf(p0.y, c2, acc.y);
            acc.z = fmaf(p1.x, c2, acc.z); acc.w = fmaf(p1.y, c2, acc.w);
            p0 = __half22float2(*(const __half2*)&w3.x); p1 = __half22float2(*(const __half2*)&w3.y);
            acc.x = fmaf(p0.x, c3, acc.x); acc.y = fmaf(p0.y, c3, acc.y);
            acc.z = fmaf(p1.x, c3, acc.z); acc.w = fmaf(p1.y, c3, acc.w);
        }
        for (; p < e; p++) {
            int2 r0 = g_csr[p];
            uint2 w0 = __ldg(&xw2[r0.x * 32 + lane]);
            float c0 = __int_as_float(r0.y);
            float2 p0 = __half22float2(*(const __half2*)&w0.x);
            float2 p1 = __half22float2(*(const __half2*)&w0.y);
            acc.x = fmaf(p0.x, c0, acc.x); acc.y = fmaf(p0.y, c0, acc.y);
            acc.z = fmaf(p1.x, c0, acc.z); acc.w = fmaf(p1.y, c0, acc.w);
        }
        float dd = g_dinv[node];
        float sc = dd * dd;
        uint2 wr = xw2[node * 32 + lane];
        float2 f0 = __half22float2(*(const __half2*)&wr.x);
        float2 f1 = __half22float2(*(const __half2*)&wr.y);
        acc.x = fmaf(f0.x, sc, acc.x) + bv.x;
        acc.y = fmaf(f0.y, sc, acc.y) + bv.y;
        acc.z = fmaf(f1.x, sc, acc.z) + bv.z;
        acc.w = fmaf(f1.y, sc, acc.w) + bv.w;
        ((float4*)g_h)[node * 32 + lane] = acc;
        ls0 += acc.x; lq0 = fmaf(acc.x, acc.x, lq0);
        ls1 += acc.y; lq1 = fmaf(acc.y, acc.y, lq1);
        ls2 += acc.z; lq2 = fmaf(acc.z, acc.z, lq2);
        ls3 += acc.w; lq3 = fmaf(acc.w, acc.w, lq3);
    }
    atomicAdd(&s_sum[lane * 4 + 0], ls0); atomicAdd(&s_sq[lane * 4 + 0], lq0);
    atomicAdd(&s_sum[lane * 4 + 1], ls1); atomicAdd(&s_sq[lane * 4 + 1], lq1);
    atomicAdd(&s_sum[lane * 4 + 2], ls2); atomicAdd(&s_sq[lane * 4 + 2], lq2);
    atomicAdd(&s_sum[lane * 4 + 3], ls3); atomicAdd(&s_sq[lane * 4 + 3], lq3);
    __syncthreads();
    if (t < Hh) {
        atomicAdd(&g_bnsum[t], s_sum[t]);
        atomicAdd(&g_bnsq [t], s_sq[t]);
    }
}

// ---------------- batch pooling ----------------
__global__ void k_bscan() {
    __shared__ int sh[1024];
    int t = threadIdx.x;
    int base = t * 4;
    int v[4]; int tot = 0;
#pragma unroll
    for (int i = 0; i < 4; i++) { v[i] = g_bcnt[base + i]; tot += v[i]; }
    sh[t] = tot; __syncthreads();
    for (int off = 1; off < 1024; off <<= 1) {
        int x = (t >= off) ? sh[t - off] : 0;
        __syncthreads();
        sh[t] += x;
        __syncthreads();
    }
    int run = sh[t] - tot;
#pragma unroll
    for (int i = 0; i < 4; i++) { g_boff[base + i] = run; run += v[i]; }
}

__global__ void k_pool(float* __restrict__ out) {
    int g = blockIdx.x;
    int c = threadIdx.x;
    int st = g_boff[g], cn = g_bcnt[g];
    float A = g_bnA[c], Bc = g_bnB[c];
    float s = 0.f, mx = -INFINITY;
    for (int r = st; r < st + cn; r++) {
        float v = fmaxf(fmaf(g_h[r * Hh + c], A, Bc), 0.f);
        s += v;
        mx = fmaxf(mx, v);
    }
    out[g * 384 + c]       = s / (float)max(cn, 1);
    out[g * 384 + 128 + c] = (cn > 0) ? mx : 0.f;
    out[g * 384 + 256 + c] = s;
}

// ---------------- launch ----------------
extern "C" void kernel_launch(void* const* d_in, const int* in_sizes, int n_in,
                              void* d_out, int out_size) {
    const float* x  = nullptr;
    const float* W1 = nullptr;
    const float* W2 = nullptr;
    const void*  ei = nullptr;
    const void*  batch = nullptr;
    const float* v128[6] = {nullptr, nullptr, nullptr, nullptr, nullptr, nullptr};
    int n128 = 0;
    for (int i = 0; i < n_in; i++) {
        switch (in_sizes[i]) {
            case Nn * FIN:  x     = (const float*)d_in[i]; break;
            case 2 * Ee:    ei    = d_in[i];               break;
            case Nn:        batch = d_in[i];               break;
            case FIN * Hh:  W1    = (const float*)d_in[i]; break;
            case Hh * Hh:   W2    = (const float*)d_in[i]; break;
            case Hh:        if (n128 < 6) v128[n128++] = (const float*)d_in[i]; break;
        }
    }
    float* out = (float*)d_out;

    k_classify<<<1, 128>>>(ei, batch, v128[0], v128[1], v128[2],
                           v128[3], v128[4], v128[5]);
    k_setup   <<<(Nn + 255) / 256, 256>>>(W2);

    k_deg     <<<(Ee + 255) / 256, 256>>>(ei, batch);
    k_scan1   <<<25, 512>>>();
    k_scan2   <<<1, 1>>>();
    k_scan3   <<<(Nn + 255) / 256, 256>>>();
    k_scatter <<<(Ee + 255) / 256, 256>>>(ei);

    // layer 1
    k_agg1    <<<Nn / 8, 256>>>(x);
    k_gemm1   <<<(Nn + 31) / 32, 128>>>(W1);      // h1 fp16 + BN1 stats fused
    k_bncoef  <<<1, 128>>>(0);

    // layer 2
    k_gemm2h  <<<(Nn + 127) / 128, 256>>>();      // in-place h1 -> xw2 (fp16)
    k_agg2h   <<<(Nn + 63) / 64, 256>>>();        // 8 nodes/warp + BN2 stats fused
    k_bncoef  <<<1, 128>>>(1);

    // pooling
    k_bscan   <<<1, 1024>>>();
    k_pool    <<<Bb, 128>>>(out);
}